// round 5
// baseline (speedup 1.0000x reference)
#include <cuda_runtime.h>
#include <mma.h>
#include <math.h>
#include <stdint.h>

using namespace nvcuda;

#define T  1024
#define Hd 1024
#define Fd 2048
#define Ed 8

#define BM 128
#define BN 128
#define BK 32
#define KP 36                 // BK + 4 floats pad; 144B rows (16B-aligned)
#define RB (KP * 4)           // row bytes = 144
#define TILE_B (BM * RB)      // 18432 bytes per buffer
#define OPAD 132

// ffn1 dyn smem: toks(512) pad to 1024, then A,B1,B3 double buffers
#define F1_OFF_A 1024
#define F1_OFF_B1 (F1_OFF_A  + 2 * TILE_B)
#define F1_OFF_B3 (F1_OFF_B1 + 2 * TILE_B)
#define SMEM_FFN1 (F1_OFF_B3 + 2 * TILE_B)          // 111616
// ffn2 dyn smem: toks+pw pad to 1024, then A,B double buffers (pool aliases A/B)
#define F2_OFF_A 1024
#define F2_OFF_B (F2_OFF_A + 2 * TILE_B)
#define SMEM_FFN2 (F2_OFF_B + 2 * TILE_B)           // 74752 (>= 1024+128*132*4 epilogue)

// ---------------- scratch ----------------
__device__ float g_inter[(size_t)Ed * T * Fd];
__device__ int   g_tok[Ed * T];
__device__ float g_pw[Ed * T];
__device__ int   g_cnt[Ed];
__device__ int   g_sel[T * 2];
__device__ float g_mult[T * 2];

__device__ __forceinline__ float tf32r(float x) {
    float r; asm("cvt.rna.tf32.f32 %0, %1;" : "=f"(r) : "f"(x)); return r;
}
__device__ __forceinline__ void cp16(void* s, const float* g) {
    unsigned a = (unsigned)__cvta_generic_to_shared(s);
    asm volatile("cp.async.cg.shared.global [%0], [%1], 16;" :: "r"(a), "l"(g));
}
#define CP_COMMIT() asm volatile("cp.async.commit_group;" ::)
#define CP_WAIT1()  asm volatile("cp.async.wait_group 1;" ::)

__device__ __forceinline__ void cvt4_inplace(char* p) {
    float4 v = *(float4*)p;
    v.x = tf32r(v.x); v.y = tf32r(v.y); v.z = tf32r(v.z); v.w = tf32r(v.w);
    *(float4*)p = v;
}

// ---------------- kernel 0 ----------------
__global__ void zero_kernel(float* __restrict__ out) {
    int i = blockIdx.x * 256 + threadIdx.x;
    out[i] = 0.0f;
    if (i < Ed) g_cnt[i] = 0;
}

// ---------------- kernel 1: router ----------------
__global__ __launch_bounds__(256) void router_kernel(
    const float* __restrict__ x, const float* __restrict__ gw,
    float* __restrict__ out_logits, int write_logits)
{
    int t = blockIdx.x, warp = threadIdx.x >> 5, lane = threadIdx.x & 31;
    const float* xr = x + (size_t)t * Hd;
    const float* gr = gw + (size_t)warp * Hd;
    float s = 0.0f;
    for (int h = lane; h < Hd; h += 32) s += xr[h] * gr[h];
    #pragma unroll
    for (int o = 16; o; o >>= 1) s += __shfl_xor_sync(0xFFFFFFFFu, s, o);

    __shared__ float sc[Ed];
    if (lane == 0) sc[warp] = s;
    __syncthreads();
    if (threadIdx.x < Ed && write_logits) out_logits[t * Ed + threadIdx.x] = sc[threadIdx.x];

    if (threadIdx.x == 0) {
        float v[Ed];
        #pragma unroll
        for (int e = 0; e < Ed; e++) v[e] = sc[e];
        int s1 = 0; float m1 = v[0];
        #pragma unroll
        for (int e = 1; e < Ed; e++) if (v[e] > m1) { m1 = v[e]; s1 = e; }
        float Z1 = 0.0f;
        #pragma unroll
        for (int e = 0; e < Ed; e++) {
            float factor = fmaxf(fabsf(v[e]), m1);
            if (!((m1 - v[e]) / factor > 0.02f)) Z1 += expf(v[e] - m1);
        }
        int s2 = -1; float m2 = -INFINITY;
        #pragma unroll
        for (int e = 0; e < Ed; e++) if (e != s1 && v[e] > m2) { m2 = v[e]; s2 = e; }
        float Z2 = 0.0f;
        #pragma unroll
        for (int e = 0; e < Ed; e++) {
            if (e == s1) continue;
            float factor = fmaxf(fabsf(v[e]), m2);
            if (!((m2 - v[e]) / factor > 0.02f)) Z2 += expf(v[e] - m2);
        }
        g_sel [t * 2 + 0] = s1;        g_sel [t * 2 + 1] = s2;
        g_mult[t * 2 + 0] = 1.0f / Z1; g_mult[t * 2 + 1] = 1.0f / Z2;
    }
}

// ---------------- kernel 2: scatter ----------------
__global__ void scatter_kernel() {
    int t = blockIdx.x * 256 + threadIdx.x;
    if (t >= T) return;
    #pragma unroll
    for (int k = 0; k < 2; k++) {
        int e = g_sel[t * 2 + k];
        int p = atomicAdd(&g_cnt[e], 1);
        g_tok[e * T + p] = t;
        g_pw [e * T + p] = g_mult[t * 2 + k];
    }
}

// ---------------- kernel 3: ffn1 -------------------------------------------
// grid (Fd/BN=16, Ed*8), 512 threads (16 warps, 4x4), warp = 32x32, dual GEMM
__global__ __launch_bounds__(512) void ffn1_kernel(
    const float* __restrict__ x,
    const float* __restrict__ w1,
    const float* __restrict__ w3)
{
    extern __shared__ char sm[];
    int e   = blockIdx.y >> 3;
    int mt  = blockIdx.y & 7;
    int cnt = g_cnt[e];
    int m0  = mt * BM;
    if (m0 >= cnt) return;
    int f0  = blockIdx.x * BN;

    int* toks = (int*)sm;
    int tid = threadIdx.x;
    if (tid < BM) {
        int i = m0 + tid;
        toks[tid] = (i < cnt) ? g_tok[e * T + i] : g_tok[e * T];
    }
    __syncthreads();

    // staging: per thread 2 chunks per tile (rows r0 and r0+64), 16B each
    int r0 = tid >> 3;              // 0..63
    int q  = (tid & 7) * 4;         // float offset within BK row
    uint32_t so = (uint32_t)r0 * RB + (uint32_t)q * 4;   // smem byte offset in tile

    const float* w1e = w1 + (size_t)e * Fd * Hd;
    const float* w3e = w3 + (size_t)e * Fd * Hd;
    const float* ag0 = x + (size_t)toks[r0]      * Hd + q;
    const float* ag1 = x + (size_t)toks[r0 + 64] * Hd + q;
    const float* b1g = w1e + (size_t)(f0 + r0) * Hd + q;
    const float* b3g = w3e + (size_t)(f0 + r0) * Hd + q;
    const size_t rowskip = (size_t)64 * Hd;

    char* smA  = sm + F1_OFF_A;
    char* smB1 = sm + F1_OFF_B1;
    char* smB3 = sm + F1_OFF_B3;

    // prologue: stage 0 into buf 0
    cp16(smA  + so,          ag0);
    cp16(smA  + so + 64*RB,  ag1);
    cp16(smB1 + so,          b1g);
    cp16(smB1 + so + 64*RB,  b1g + rowskip);
    cp16(smB3 + so,          b3g);
    cp16(smB3 + so + 64*RB,  b3g + rowskip);
    CP_COMMIT();

    wmma::fragment<wmma::matrix_a, 16,16,8, wmma::precision::tf32, wmma::row_major> fa[2];
    wmma::fragment<wmma::matrix_b, 16,16,8, wmma::precision::tf32, wmma::col_major> fb1[2], fb3[2];
    wmma::fragment<wmma::accumulator, 16,16,8, float> acc1[2][2], acc3[2][2];
    #pragma unroll
    for (int i = 0; i < 2; i++)
        #pragma unroll
        for (int j = 0; j < 2; j++) { wmma::fill_fragment(acc1[i][j], 0.f); wmma::fill_fragment(acc3[i][j], 0.f); }

    int wid = tid >> 5;
    int wm  = wid >> 2;     // 0..3 -> 32 rows
    int wn  = wid & 3;      // 0..3 -> 32 cols

    int buf = 0;
    for (int k0 = 0; k0 < Hd; k0 += BK) {
        if (k0 + BK < Hd) {
            int nb = buf ^ 1;
            cp16(smA  + nb*TILE_B + so,         ag0 + k0 + BK);
            cp16(smA  + nb*TILE_B + so + 64*RB, ag1 + k0 + BK);
            cp16(smB1 + nb*TILE_B + so,         b1g + k0 + BK);
            cp16(smB1 + nb*TILE_B + so + 64*RB, b1g + rowskip + k0 + BK);
            cp16(smB3 + nb*TILE_B + so,         b3g + k0 + BK);
            cp16(smB3 + nb*TILE_B + so + 64*RB, b3g + rowskip + k0 + BK);
        }
        CP_COMMIT();
        CP_WAIT1();
        __syncthreads();

        // convert current buffer in place (each element exactly once)
        cvt4_inplace(smA  + buf*TILE_B + so);
        cvt4_inplace(smA  + buf*TILE_B + so + 64*RB);
        cvt4_inplace(smB1 + buf*TILE_B + so);
        cvt4_inplace(smB1 + buf*TILE_B + so + 64*RB);
        cvt4_inplace(smB3 + buf*TILE_B + so);
        cvt4_inplace(smB3 + buf*TILE_B + so + 64*RB);
        __syncthreads();

        const float* Ab  = (const float*)(smA  + buf*TILE_B);
        const float* B1b = (const float*)(smB1 + buf*TILE_B);
        const float* B3b = (const float*)(smB3 + buf*TILE_B);
        #pragma unroll
        for (int ks = 0; ks < BK; ks += 8) {
            wmma::load_matrix_sync(fa[0],  Ab  + (wm*32     ) * KP + ks, KP);
            wmma::load_matrix_sync(fa[1],  Ab  + (wm*32 + 16) * KP + ks, KP);
            wmma::load_matrix_sync(fb1[0], B1b + (wn*32     ) * KP + ks, KP);
            wmma::load_matrix_sync(fb1[1], B1b + (wn*32 + 16) * KP + ks, KP);
            wmma::load_matrix_sync(fb3[0], B3b + (wn*32     ) * KP + ks, KP);
            wmma::load_matrix_sync(fb3[1], B3b + (wn*32 + 16) * KP + ks, KP);
            #pragma unroll
            for (int i = 0; i < 2; i++)
                #pragma unroll
                for (int j = 0; j < 2; j++) {
                    wmma::mma_sync(acc1[i][j], fa[i], fb1[j], acc1[i][j]);
                    wmma::mma_sync(acc3[i][j], fa[i], fb3[j], acc3[i][j]);
                }
        }
        __syncthreads();
        buf ^= 1;
    }

    // epilogue: silu(h1)*h3 -> g_inter
    float* ob = &g_inter[((size_t)e * T + m0 + wm*32) * Fd + f0 + wn*32];
    #pragma unroll
    for (int i = 0; i < 2; i++)
        #pragma unroll
        for (int j = 0; j < 2; j++) {
            #pragma unroll
            for (int el = 0; el < acc1[i][j].num_elements; el++) {
                float h1 = acc1[i][j].x[el], h3 = acc3[i][j].x[el];
                acc1[i][j].x[el] = h1 / (1.0f + expf(-h1)) * h3;
            }
            wmma::store_matrix_sync(ob + (size_t)i*16*Fd + j*16, acc1[i][j], Fd, wmma::mem_row_major);
        }
}

// ---------------- kernel 4: ffn2 -------------------------------------------
// grid (Hd/BN=8, Ed*8), 512 threads, warp 32x32
__global__ __launch_bounds__(512) void ffn2_kernel(
    const float* __restrict__ w2, float* __restrict__ out)
{
    extern __shared__ char sm[];
    int e   = blockIdx.y >> 3;
    int mt  = blockIdx.y & 7;
    int cnt = g_cnt[e];
    int m0  = mt * BM;
    if (m0 >= cnt) return;
    int h0  = blockIdx.x * BN;

    int*   toks = (int*)sm;
    float* pws  = (float*)(sm + 512);
    int tid = threadIdx.x;
    if (tid < BM) {
        int i = m0 + tid;
        toks[tid] = (i < cnt) ? g_tok[e * T + i] : 0;
        pws [tid] = (i < cnt) ? g_pw [e * T + i] : 0.0f;
    }
    __syncthreads();

    int r0 = tid >> 3;
    int q  = (tid & 7) * 4;
    uint32_t so = (uint32_t)r0 * RB + (uint32_t)q * 4;

    const float* ag = &g_inter[((size_t)e * T + m0 + r0) * Fd + q];
    const float* bg = w2 + ((size_t)e * Hd + h0 + r0) * Fd + q;
    const size_t rowskipA = (size_t)64 * Fd;
    const size_t rowskipB = (size_t)64 * Fd;

    char* smA = sm + F2_OFF_A;
    char* smB = sm + F2_OFF_B;

    cp16(smA + so,         ag);
    cp16(smA + so + 64*RB, ag + rowskipA);
    cp16(smB + so,         bg);
    cp16(smB + so + 64*RB, bg + rowskipB);
    CP_COMMIT();

    wmma::fragment<wmma::matrix_a, 16,16,8, wmma::precision::tf32, wmma::row_major> fa[2];
    wmma::fragment<wmma::matrix_b, 16,16,8, wmma::precision::tf32, wmma::col_major> fb[2];
    wmma::fragment<wmma::accumulator, 16,16,8, float> acc[2][2];
    #pragma unroll
    for (int i = 0; i < 2; i++)
        #pragma unroll
        for (int j = 0; j < 2; j++) wmma::fill_fragment(acc[i][j], 0.f);

    int wid = tid >> 5;
    int wm  = wid >> 2;
    int wn  = wid & 3;

    int buf = 0;
    for (int k0 = 0; k0 < Fd; k0 += BK) {
        if (k0 + BK < Fd) {
            int nb = buf ^ 1;
            cp16(smA + nb*TILE_B + so,         ag + k0 + BK);
            cp16(smA + nb*TILE_B + so + 64*RB, ag + rowskipA + k0 + BK);
            cp16(smB + nb*TILE_B + so,         bg + k0 + BK);
            cp16(smB + nb*TILE_B + so + 64*RB, bg + rowskipB + k0 + BK);
        }
        CP_COMMIT();
        CP_WAIT1();
        __syncthreads();

        cvt4_inplace(smA + buf*TILE_B + so);
        cvt4_inplace(smA + buf*TILE_B + so + 64*RB);
        cvt4_inplace(smB + buf*TILE_B + so);
        cvt4_inplace(smB + buf*TILE_B + so + 64*RB);
        __syncthreads();

        const float* Ab = (const float*)(smA + buf*TILE_B);
        const float* Bb = (const float*)(smB + buf*TILE_B);
        #pragma unroll
        for (int ks = 0; ks < BK; ks += 8) {
            wmma::load_matrix_sync(fa[0], Ab + (wm*32     ) * KP + ks, KP);
            wmma::load_matrix_sync(fa[1], Ab + (wm*32 + 16) * KP + ks, KP);
            wmma::load_matrix_sync(fb[0], Bb + (wn*32     ) * KP + ks, KP);
            wmma::load_matrix_sync(fb[1], Bb + (wn*32 + 16) * KP + ks, KP);
            #pragma unroll
            for (int i = 0; i < 2; i++)
                #pragma unroll
                for (int j = 0; j < 2; j++)
                    wmma::mma_sync(acc[i][j], fa[i], fb[j], acc[i][j]);
        }
        __syncthreads();
        buf ^= 1;
    }

    // epilogue: stage to smem pool (aliases A/B buffers), scale by pw, atomicAdd
    __syncthreads();
    float* pool = (float*)(sm + F2_OFF_A);
    #pragma unroll
    for (int i = 0; i < 2; i++)
        #pragma unroll
        for (int j = 0; j < 2; j++)
            wmma::store_matrix_sync(
                pool + (size_t)(wm*32 + i*16) * OPAD + wn*32 + j*16,
                acc[i][j], OPAD, wmma::mem_row_major);
    __syncthreads();

    for (int idx = tid; idx < BM * BN; idx += 512) {
        int r = idx >> 7;          // 0..127
        int c = idx & 127;         // 0..127
        if (m0 + r < cnt)
            atomicAdd(&out[(size_t)toks[r] * Hd + h0 + c], pws[r] * pool[r * OPAD + c]);
    }
}

// ---------------- launch ----------------
extern "C" void kernel_launch(void* const* d_in, const int* in_sizes, int n_in,
                              void* d_out, int out_size)
{
    const float* x  = (const float*)d_in[0];
    const float* gw = (const float*)d_in[1];
    const float* w1 = (const float*)d_in[2];
    const float* w2 = (const float*)d_in[3];
    const float* w3 = (const float*)d_in[4];
    float* out = (float*)d_out;

    cudaFuncSetAttribute(ffn1_kernel, cudaFuncAttributeMaxDynamicSharedMemorySize, SMEM_FFN1);
    cudaFuncSetAttribute(ffn2_kernel, cudaFuncAttributeMaxDynamicSharedMemorySize, SMEM_FFN2);

    int write_logits = (out_size >= T * Hd + T * Ed) ? 1 : 0;
    float* out_logits = out + (size_t)T * Hd;

    zero_kernel   <<<(T * Hd) / 256, 256>>>(out);
    router_kernel <<<T, 256>>>(x, gw, out_logits, write_logits);
    scatter_kernel<<<T / 256, 256>>>();

    dim3 g1(Fd / BN, Ed * 8);
    ffn1_kernel<<<g1, 512, SMEM_FFN1>>>(x, w1, w3);

    dim3 g2(Hd / BN, Ed * 8);
    ffn2_kernel<<<g2, 512, SMEM_FFN2>>>(w2, out);
}

// round 6
// speedup vs baseline: 1.2058x; 1.2058x over previous
#include <cuda_runtime.h>
#include <mma.h>
#include <math.h>
#include <stdint.h>

using namespace nvcuda;

#define T  1024
#define Hd 1024
#define Fd 2048
#define Ed 8

#define BM 128
#define BN 64
#define BK 16
#define KP 20                  // BK + 4 pad floats
#define RB (KP * 4)            // 80 B per row
#define A_BYTES (BM * RB)      // 10240
#define B_BYTES (BN * RB)      // 5120
#define NSTAGE 3
#define OPAD 68

// ffn1 smem: toks pad 1024 | A[3] | B1[3] | B3[3]
#define F1_A   1024
#define F1_B1  (F1_A  + NSTAGE * A_BYTES)
#define F1_B3  (F1_B1 + NSTAGE * B_BYTES)
#define SMEM_FFN1 (F1_B3 + NSTAGE * B_BYTES)   // 62464
// ffn2 smem: toks/pw pad 1024 | A[3] | B[3]
#define F2_A   1024
#define F2_B   (F2_A + NSTAGE * A_BYTES)
#define SMEM_FFN2 (F2_B + NSTAGE * B_BYTES)    // 47104

// ---------------- scratch ----------------
__device__ float g_inter[(size_t)Ed * T * Fd];
__device__ int   g_tok[Ed * T];
__device__ float g_pw[Ed * T];
__device__ int   g_cnt[Ed];
__device__ int   g_sel[T * 2];
__device__ float g_mult[T * 2];

__device__ __forceinline__ float tf32r(float x) {
    float r; asm("cvt.rna.tf32.f32 %0, %1;" : "=f"(r) : "f"(x)); return r;
}
__device__ __forceinline__ void cp16(void* s, const float* g) {
    unsigned a = (unsigned)__cvta_generic_to_shared(s);
    asm volatile("cp.async.cg.shared.global [%0], [%1], 16;" :: "r"(a), "l"(g));
}
#define CP_COMMIT() asm volatile("cp.async.commit_group;" ::)
#define CP_WAIT1()  asm volatile("cp.async.wait_group 1;" ::)

// ---------------- kernel 0 ----------------
__global__ void zero_kernel(float* __restrict__ out) {
    int i = blockIdx.x * 256 + threadIdx.x;
    out[i] = 0.0f;
    if (i < Ed) g_cnt[i] = 0;
}

// ---------------- kernel 1: router ----------------
__global__ __launch_bounds__(256) void router_kernel(
    const float* __restrict__ x, const float* __restrict__ gw,
    float* __restrict__ out_logits, int write_logits)
{
    int t = blockIdx.x, warp = threadIdx.x >> 5, lane = threadIdx.x & 31;
    const float* xr = x + (size_t)t * Hd;
    const float* gr = gw + (size_t)warp * Hd;
    float s = 0.0f;
    for (int h = lane; h < Hd; h += 32) s += xr[h] * gr[h];
    #pragma unroll
    for (int o = 16; o; o >>= 1) s += __shfl_xor_sync(0xFFFFFFFFu, s, o);

    __shared__ float sc[Ed];
    if (lane == 0) sc[warp] = s;
    __syncthreads();
    if (threadIdx.x < Ed && write_logits) out_logits[t * Ed + threadIdx.x] = sc[threadIdx.x];

    if (threadIdx.x == 0) {
        float v[Ed];
        #pragma unroll
        for (int e = 0; e < Ed; e++) v[e] = sc[e];
        int s1 = 0; float m1 = v[0];
        #pragma unroll
        for (int e = 1; e < Ed; e++) if (v[e] > m1) { m1 = v[e]; s1 = e; }
        float Z1 = 0.0f;
        #pragma unroll
        for (int e = 0; e < Ed; e++) {
            float factor = fmaxf(fabsf(v[e]), m1);
            if (!((m1 - v[e]) / factor > 0.02f)) Z1 += expf(v[e] - m1);
        }
        int s2 = -1; float m2 = -INFINITY;
        #pragma unroll
        for (int e = 0; e < Ed; e++) if (e != s1 && v[e] > m2) { m2 = v[e]; s2 = e; }
        float Z2 = 0.0f;
        #pragma unroll
        for (int e = 0; e < Ed; e++) {
            if (e == s1) continue;
            float factor = fmaxf(fabsf(v[e]), m2);
            if (!((m2 - v[e]) / factor > 0.02f)) Z2 += expf(v[e] - m2);
        }
        g_sel [t * 2 + 0] = s1;        g_sel [t * 2 + 1] = s2;
        g_mult[t * 2 + 0] = 1.0f / Z1; g_mult[t * 2 + 1] = 1.0f / Z2;
    }
}

// ---------------- kernel 2: scatter ----------------
__global__ void scatter_kernel() {
    int t = blockIdx.x * 256 + threadIdx.x;
    if (t >= T) return;
    #pragma unroll
    for (int k = 0; k < 2; k++) {
        int e = g_sel[t * 2 + k];
        int p = atomicAdd(&g_cnt[e], 1);
        g_tok[e * T + p] = t;
        g_pw [e * T + p] = g_mult[t * 2 + k];
    }
}

// ---------------- kernel 3: ffn1 -------------------------------------------
// grid (Fd/BN=32, Ed*8=64), 256 threads (8 warps, 4m x 2n), warp 32x32 dual
__global__ __launch_bounds__(256, 2) void ffn1_kernel(
    const float* __restrict__ x,
    const float* __restrict__ w1,
    const float* __restrict__ w3)
{
    extern __shared__ char sm[];
    int e   = blockIdx.y >> 3;
    int mt  = blockIdx.y & 7;
    int cnt = g_cnt[e];
    int m0  = mt * BM;
    if (m0 >= cnt) return;
    int f0  = blockIdx.x * BN;

    int* toks = (int*)sm;
    int tid = threadIdx.x;
    if (tid < BM) {
        int i = m0 + tid;
        toks[tid] = (i < cnt) ? g_tok[e * T + i] : g_tok[e * T];
    }
    __syncthreads();

    // A: 2 chunks/thread (rows 0..127); B1,B3: 1 chunk/thread (rows 0..63)
    int ar0 = tid >> 2;                 // 0..63
    int aq  = (tid & 3) * 4;            // 0,4,8,12
    uint32_t soA0 = (uint32_t)ar0 * RB + aq * 4;
    uint32_t soA1 = soA0 + 64 * RB;
    uint32_t soB  = soA0;

    const float* w1e = w1 + (size_t)e * Fd * Hd;
    const float* w3e = w3 + (size_t)e * Fd * Hd;
    const float* ag0 = x + (size_t)toks[ar0]      * Hd + aq;
    const float* ag1 = x + (size_t)toks[ar0 + 64] * Hd + aq;
    const float* b1g = w1e + (size_t)(f0 + ar0) * Hd + aq;
    const float* b3g = w3e + (size_t)(f0 + ar0) * Hd + aq;

    char* smA  = sm + F1_A;
    char* smB1 = sm + F1_B1;
    char* smB3 = sm + F1_B3;

    // prologue: stages 0,1
    #pragma unroll
    for (int s = 0; s < NSTAGE - 1; s++) {
        int k0 = s * BK;
        cp16(smA  + s * A_BYTES + soA0, ag0 + k0);
        cp16(smA  + s * A_BYTES + soA1, ag1 + k0);
        cp16(smB1 + s * B_BYTES + soB,  b1g + k0);
        cp16(smB3 + s * B_BYTES + soB,  b3g + k0);
        CP_COMMIT();
    }

    wmma::fragment<wmma::matrix_a, 16,16,8, wmma::precision::tf32, wmma::row_major> fa[2];
    wmma::fragment<wmma::matrix_b, 16,16,8, wmma::precision::tf32, wmma::col_major> fb1[2], fb3[2];
    wmma::fragment<wmma::accumulator, 16,16,8, float> acc1[2][2], acc3[2][2];
    #pragma unroll
    for (int i = 0; i < 2; i++)
        #pragma unroll
        for (int j = 0; j < 2; j++) { wmma::fill_fragment(acc1[i][j], 0.f); wmma::fill_fragment(acc3[i][j], 0.f); }

    int wid = tid >> 5;
    int wm  = wid >> 1;     // 0..3
    int wn  = wid & 1;      // 0..1

    int cur = 0, nxt = NSTAGE - 1;
    const int NS = Hd / BK;  // 64
    for (int s = 0; s < NS; s++) {
        CP_WAIT1();
        __syncthreads();
        // prefetch stage s+2 into buffer nxt (safe: all warps passed sync)
        if (s + NSTAGE - 1 < NS) {
            int k0 = (s + NSTAGE - 1) * BK;
            cp16(smA  + nxt * A_BYTES + soA0, ag0 + k0);
            cp16(smA  + nxt * A_BYTES + soA1, ag1 + k0);
            cp16(smB1 + nxt * B_BYTES + soB,  b1g + k0);
            cp16(smB3 + nxt * B_BYTES + soB,  b3g + k0);
        }
        CP_COMMIT();

        const float* Ab  = (const float*)(smA  + cur * A_BYTES);
        const float* B1b = (const float*)(smB1 + cur * B_BYTES);
        const float* B3b = (const float*)(smB3 + cur * B_BYTES);
        #pragma unroll
        for (int ks = 0; ks < BK; ks += 8) {
            wmma::load_matrix_sync(fa[0],  Ab  + (wm*32     ) * KP + ks, KP);
            wmma::load_matrix_sync(fa[1],  Ab  + (wm*32 + 16) * KP + ks, KP);
            wmma::load_matrix_sync(fb1[0], B1b + (wn*32     ) * KP + ks, KP);
            wmma::load_matrix_sync(fb1[1], B1b + (wn*32 + 16) * KP + ks, KP);
            wmma::load_matrix_sync(fb3[0], B3b + (wn*32     ) * KP + ks, KP);
            wmma::load_matrix_sync(fb3[1], B3b + (wn*32 + 16) * KP + ks, KP);
            #pragma unroll
            for (int q = 0; q < 4; q++) {
                fa[0].x[q] = tf32r(fa[0].x[q]);  fa[1].x[q] = tf32r(fa[1].x[q]);
                fb1[0].x[q] = tf32r(fb1[0].x[q]); fb1[1].x[q] = tf32r(fb1[1].x[q]);
                fb3[0].x[q] = tf32r(fb3[0].x[q]); fb3[1].x[q] = tf32r(fb3[1].x[q]);
            }
            #pragma unroll
            for (int i = 0; i < 2; i++)
                #pragma unroll
                for (int j = 0; j < 2; j++) {
                    wmma::mma_sync(acc1[i][j], fa[i], fb1[j], acc1[i][j]);
                    wmma::mma_sync(acc3[i][j], fa[i], fb3[j], acc3[i][j]);
                }
        }
        cur = (cur + 1 == NSTAGE) ? 0 : cur + 1;
        nxt = (nxt + 1 == NSTAGE) ? 0 : nxt + 1;
    }

    float* ob = &g_inter[((size_t)e * T + m0 + wm*32) * Fd + f0 + wn*32];
    #pragma unroll
    for (int i = 0; i < 2; i++)
        #pragma unroll
        for (int j = 0; j < 2; j++) {
            #pragma unroll
            for (int el = 0; el < acc1[i][j].num_elements; el++) {
                float h1 = acc1[i][j].x[el], h3 = acc3[i][j].x[el];
                acc1[i][j].x[el] = h1 / (1.0f + expf(-h1)) * h3;
            }
            wmma::store_matrix_sync(ob + (size_t)i*16*Fd + j*16, acc1[i][j], Fd, wmma::mem_row_major);
        }
}

// ---------------- kernel 4: ffn2 -------------------------------------------
// grid (Hd/BN=16, Ed*8=64), 256 threads, warp 32x32
__global__ __launch_bounds__(256, 2) void ffn2_kernel(
    const float* __restrict__ w2, float* __restrict__ out)
{
    extern __shared__ char sm[];
    int e   = blockIdx.y >> 3;
    int mt  = blockIdx.y & 7;
    int cnt = g_cnt[e];
    int m0  = mt * BM;
    if (m0 >= cnt) return;
    int h0  = blockIdx.x * BN;

    int*   toks = (int*)sm;
    float* pws  = (float*)(sm + 512);
    int tid = threadIdx.x;
    if (tid < BM) {
        int i = m0 + tid;
        toks[tid] = (i < cnt) ? g_tok[e * T + i] : 0;
        pws [tid] = (i < cnt) ? g_pw [e * T + i] : 0.0f;
    }
    __syncthreads();

    int ar0 = tid >> 2;
    int aq  = (tid & 3) * 4;
    uint32_t soA0 = (uint32_t)ar0 * RB + aq * 4;
    uint32_t soA1 = soA0 + 64 * RB;
    uint32_t soB  = soA0;

    const float* ag0 = &g_inter[((size_t)e * T + m0 + ar0     ) * Fd + aq];
    const float* ag1 = &g_inter[((size_t)e * T + m0 + ar0 + 64) * Fd + aq];
    const float* bg  = w2 + ((size_t)e * Hd + h0 + ar0) * Fd + aq;

    char* smA = sm + F2_A;
    char* smB = sm + F2_B;

    #pragma unroll
    for (int s = 0; s < NSTAGE - 1; s++) {
        int k0 = s * BK;
        cp16(smA + s * A_BYTES + soA0, ag0 + k0);
        cp16(smA + s * A_BYTES + soA1, ag1 + k0);
        cp16(smB + s * B_BYTES + soB,  bg  + k0);
        CP_COMMIT();
    }

    wmma::fragment<wmma::matrix_a, 16,16,8, wmma::precision::tf32, wmma::row_major> fa[2];
    wmma::fragment<wmma::matrix_b, 16,16,8, wmma::precision::tf32, wmma::col_major> fb[2];
    wmma::fragment<wmma::accumulator, 16,16,8, float> acc[2][2];
    #pragma unroll
    for (int i = 0; i < 2; i++)
        #pragma unroll
        for (int j = 0; j < 2; j++) wmma::fill_fragment(acc[i][j], 0.f);

    int wid = tid >> 5;
    int wm  = wid >> 1;
    int wn  = wid & 1;

    int cur = 0, nxt = NSTAGE - 1;
    const int NS = Fd / BK;   // 128
    for (int s = 0; s < NS; s++) {
        CP_WAIT1();
        __syncthreads();
        if (s + NSTAGE - 1 < NS) {
            int k0 = (s + NSTAGE - 1) * BK;
            cp16(smA + nxt * A_BYTES + soA0, ag0 + k0);
            cp16(smA + nxt * A_BYTES + soA1, ag1 + k0);
            cp16(smB + nxt * B_BYTES + soB,  bg  + k0);
        }
        CP_COMMIT();

        const float* Ab = (const float*)(smA + cur * A_BYTES);
        const float* Bb = (const float*)(smB + cur * B_BYTES);
        #pragma unroll
        for (int ks = 0; ks < BK; ks += 8) {
            wmma::load_matrix_sync(fa[0], Ab + (wm*32     ) * KP + ks, KP);
            wmma::load_matrix_sync(fa[1], Ab + (wm*32 + 16) * KP + ks, KP);
            wmma::load_matrix_sync(fb[0], Bb + (wn*32     ) * KP + ks, KP);
            wmma::load_matrix_sync(fb[1], Bb + (wn*32 + 16) * KP + ks, KP);
            #pragma unroll
            for (int q = 0; q < 4; q++) {
                fa[0].x[q] = tf32r(fa[0].x[q]); fa[1].x[q] = tf32r(fa[1].x[q]);
                fb[0].x[q] = tf32r(fb[0].x[q]); fb[1].x[q] = tf32r(fb[1].x[q]);
            }
            #pragma unroll
            for (int i = 0; i < 2; i++)
                #pragma unroll
                for (int j = 0; j < 2; j++)
                    wmma::mma_sync(acc[i][j], fa[i], fb[j], acc[i][j]);
        }
        cur = (cur + 1 == NSTAGE) ? 0 : cur + 1;
        nxt = (nxt + 1 == NSTAGE) ? 0 : nxt + 1;
    }

    // epilogue: stage to smem (alias A/B region), scale by pw, atomicAdd
    __syncthreads();
    float* pool = (float*)(sm + F2_A);
    #pragma unroll
    for (int i = 0; i < 2; i++)
        #pragma unroll
        for (int j = 0; j < 2; j++)
            wmma::store_matrix_sync(
                pool + (size_t)(wm*32 + i*16) * OPAD + wn*32 + j*16,
                acc[i][j], OPAD, wmma::mem_row_major);
    __syncthreads();

    for (int idx = tid; idx < BM * BN; idx += 256) {
        int r = idx >> 6;
        int c = idx & 63;
        if (m0 + r < cnt)
            atomicAdd(&out[(size_t)toks[r] * Hd + h0 + c], pws[r] * pool[r * OPAD + c]);
    }
}

// ---------------- launch ----------------
extern "C" void kernel_launch(void* const* d_in, const int* in_sizes, int n_in,
                              void* d_out, int out_size)
{
    const float* x  = (const float*)d_in[0];
    const float* gw = (const float*)d_in[1];
    const float* w1 = (const float*)d_in[2];
    const float* w2 = (const float*)d_in[3];
    const float* w3 = (const float*)d_in[4];
    float* out = (float*)d_out;

    cudaFuncSetAttribute(ffn1_kernel, cudaFuncAttributeMaxDynamicSharedMemorySize, SMEM_FFN1);
    cudaFuncSetAttribute(ffn2_kernel, cudaFuncAttributeMaxDynamicSharedMemorySize, SMEM_FFN2);

    int write_logits = (out_size >= T * Hd + T * Ed) ? 1 : 0;
    float* out_logits = out + (size_t)T * Hd;

    zero_kernel   <<<(T * Hd) / 256, 256>>>(out);
    router_kernel <<<T, 256>>>(x, gw, out_logits, write_logits);
    scatter_kernel<<<T / 256, 256>>>();

    dim3 g1(Fd / BN, Ed * 8);
    ffn1_kernel<<<g1, 256, SMEM_FFN1>>>(x, w1, w3);

    dim3 g2(Hd / BN, Ed * 8);
    ffn2_kernel<<<g2, 256, SMEM_FFN2>>>(w2, out);
}